// round 3
// baseline (speedup 1.0000x reference)
#include <cuda_runtime.h>
#include <cstddef>

// Problem constants
#define N_NODES 50000
#define K_NB    32
#define D_IN    512
#define D_HID   128
#define D_OUT   64

// Scratch (device globals: allocation-free, graph-capturable)
__device__ float g_h [(size_t)N_NODES * D_HID];   // feat@W1+b1
__device__ float g_h1[(size_t)N_NODES * D_HID];   // relu(median(...))
__device__ float g_g [(size_t)N_NODES * D_OUT];   // h1@W2+b2

// ---------------------------------------------------------------------------
// Tiled fp32 GEMM with bias:  C[M,N] = A[M,K] @ B[K,N] + bias[N]
// A row-major, B row-major. BN == N for both layer shapes.
// ---------------------------------------------------------------------------
template<int BM, int BN, int BK, int TM, int TN>
__global__ __launch_bounds__((BM/TM)*(BN/TN))
void gemm_bias_kernel(const float* __restrict__ A, const float* __restrict__ B,
                      const float* __restrict__ bias, float* __restrict__ C,
                      int M, int N, int K) {
    constexpr int NT = (BM / TM) * (BN / TN);
    __shared__ float As[BK * BM];   // transposed: As[k*BM + m]
    __shared__ float Bs[BK * BN];   // Bs[k*BN + n]

    const int tid  = threadIdx.x;
    const int row0 = blockIdx.x * BM;
    const int tr   = tid / (BN / TN);
    const int tc   = tid % (BN / TN);

    float acc[TM][TN];
#pragma unroll
    for (int m = 0; m < TM; ++m)
#pragma unroll
        for (int n = 0; n < TN; ++n) acc[m][n] = 0.0f;

    for (int k0 = 0; k0 < K; k0 += BK) {
        // Load A tile (vectorized along K), store transposed into smem
        for (int i = tid; i < BM * BK / 4; i += NT) {
            int r  = i / (BK / 4);
            int c4 = i % (BK / 4);
            int grow = row0 + r;
            float4 val = make_float4(0.f, 0.f, 0.f, 0.f);
            if (grow < M)
                val = *(const float4*)&A[(size_t)grow * K + k0 + c4 * 4];
            As[(c4 * 4 + 0) * BM + r] = val.x;
            As[(c4 * 4 + 1) * BM + r] = val.y;
            As[(c4 * 4 + 2) * BM + r] = val.z;
            As[(c4 * 4 + 3) * BM + r] = val.w;
        }
        // Load B tile (coalesced; N % BN == 0, K % BK == 0)
        for (int i = tid; i < BK * BN / 4; i += NT) {
            int r  = i / (BN / 4);
            int c4 = i % (BN / 4);
            *(float4*)&Bs[r * BN + c4 * 4] =
                *(const float4*)&B[(size_t)(k0 + r) * N + c4 * 4];
        }
        __syncthreads();

#pragma unroll
        for (int k = 0; k < BK; ++k) {
            float a[TM], b[TN];
#pragma unroll
            for (int m = 0; m < TM; ++m) a[m] = As[k * BM + tr * TM + m];
#pragma unroll
            for (int n = 0; n < TN; ++n) b[n] = Bs[k * BN + tc * TN + n];
#pragma unroll
            for (int m = 0; m < TM; ++m)
#pragma unroll
                for (int n = 0; n < TN; ++n)
                    acc[m][n] = fmaf(a[m], b[n], acc[m][n]);
        }
        __syncthreads();
    }

#pragma unroll
    for (int m = 0; m < TM; ++m) {
        int grow = row0 + tr * TM + m;
        if (grow < M) {
#pragma unroll
            for (int n = 0; n < TN; ++n)
                C[(size_t)grow * N + tc * TN + n] = acc[m][n] + bias[tc * TN + n];
        }
    }
}

// ---------------------------------------------------------------------------
// In-register ascending bitonic sort of 16 floats (fully unrolled -> FMNMX)
// ---------------------------------------------------------------------------
__device__ __forceinline__ void sort16(float* v) {
#pragma unroll
    for (int k = 2; k <= 16; k <<= 1) {
#pragma unroll
        for (int j = k >> 1; j > 0; j >>= 1) {
#pragma unroll
            for (int i = 0; i < 16; ++i) {
                int l = i ^ j;
                if (l > i) {
                    float a = v[i], b = v[l];
                    float lo = fminf(a, b), hi = fmaxf(a, b);
                    bool up = ((i & k) == 0);
                    v[i] = up ? lo : hi;
                    v[l] = up ? hi : lo;
                }
            }
        }
    }
}

// Lower median (rank 15, 0-indexed) of 32 values:
// sort both 16-halves ascending, then bitonic-halver: the multiset
// { min(v[i], v[31-i]) } is exactly the 16 smallest; its max is rank-15.
__device__ __forceinline__ float median32(float* v) {
    sort16(v);
    sort16(v + 16);
    float med = fminf(v[0], v[31]);
#pragma unroll
    for (int i = 1; i < 16; ++i)
        med = fmaxf(med, fminf(v[i], v[31 - i]));
    return med;
}

// ---------------------------------------------------------------------------
// Layer-1 median + ReLU: one block per node, 128 threads (one per feature).
// NOTE: neighbors buffer is int32 (JAX x64-disabled downcasts int64).
// ---------------------------------------------------------------------------
__global__ __launch_bounds__(D_HID)
void median_relu_128(const int* __restrict__ nb) {
    const int n = blockIdx.x;
    const int d = threadIdx.x;

    __shared__ int sidx[K_NB];
    if (d < K_NB) sidx[d] = nb[(size_t)n * K_NB + d];
    __syncthreads();

    float v[K_NB];
#pragma unroll
    for (int k = 0; k < K_NB; ++k)
        v[k] = __ldg(&g_h[(size_t)sidx[k] * D_HID + d]);

    float med = median32(v);
    g_h1[(size_t)n * D_HID + d] = fmaxf(med, 0.0f);
}

// ---------------------------------------------------------------------------
// Layer-2 median: 2 nodes per block (128 threads), 64 features each.
// ---------------------------------------------------------------------------
__global__ __launch_bounds__(128)
void median_64(const int* __restrict__ nb, float* __restrict__ out) {
    const int local = threadIdx.x >> 6;              // 0..1
    const int n = blockIdx.x * 2 + local;
    const int d = threadIdx.x & 63;

    __shared__ int sidx[2 * K_NB];
    if (threadIdx.x < 2 * K_NB)
        sidx[threadIdx.x] = nb[(size_t)(blockIdx.x * 2) * K_NB + threadIdx.x];
    __syncthreads();

    float v[K_NB];
#pragma unroll
    for (int k = 0; k < K_NB; ++k)
        v[k] = __ldg(&g_g[(size_t)sidx[local * K_NB + k] * D_OUT + d]);

    out[(size_t)n * D_OUT + d] = median32(v);
}

// ---------------------------------------------------------------------------
extern "C" void kernel_launch(void* const* d_in, const int* in_sizes, int n_in,
                              void* d_out, int out_size) {
    const float* feat = (const float*)d_in[0];
    const float* W1   = (const float*)d_in[1];
    const float* b1   = (const float*)d_in[2];
    const float* W2   = (const float*)d_in[3];
    const float* b2   = (const float*)d_in[4];
    const int*   nb   = (const int*)d_in[5];
    float* out = (float*)d_out;

    void *ph = nullptr, *ph1 = nullptr, *pg = nullptr;
    cudaGetSymbolAddress(&ph,  g_h);
    cudaGetSymbolAddress(&ph1, g_h1);
    cudaGetSymbolAddress(&pg,  g_g);
    float* h  = (float*)ph;
    float* h1 = (float*)ph1;
    float* g  = (float*)pg;

    // 1) h = feat @ W1 + b1   [50000,512] x [512,128]
    {
        constexpr int BM = 128, BN = 128, BK = 16, TM = 8, TN = 8;
        dim3 grid((N_NODES + BM - 1) / BM);
        gemm_bias_kernel<BM, BN, BK, TM, TN>
            <<<grid, (BM / TM) * (BN / TN)>>>(feat, W1, b1, h,
                                              N_NODES, D_HID, D_IN);
    }

    // 2) h1 = relu(median_k h[nb])
    median_relu_128<<<N_NODES, D_HID>>>(nb);

    // 3) g = h1 @ W2 + b2   [50000,128] x [128,64]
    {
        constexpr int BM = 128, BN = 64, BK = 16, TM = 8, TN = 8;
        dim3 grid((N_NODES + BM - 1) / BM);
        gemm_bias_kernel<BM, BN, BK, TM, TN>
            <<<grid, (BM / TM) * (BN / TN)>>>(h1, W2, b2, g,
                                              N_NODES, D_OUT, D_HID);
    }

    // 4) out = median_k g[nb]
    median_64<<<N_NODES / 2, 128>>>(nb, out);
}